// round 1
// baseline (speedup 1.0000x reference)
#include <cuda_runtime.h>

#define B 16
#define T 512
#define D 256
#define HS 512
#define DA 64
#define R 8
#define G4 (4*HS)   // 2048
#define NCTA 128
#define SCAN_THREADS 512
#define HPAD 516    // 512 + 4 padding to kill bank conflicts

// -------- scratch (static device arrays: allocation-free) --------
__device__ float g_s [B*T*R];
__device__ float g_e [B*T*R];
__device__ float g_iz[B*T*R];
__device__ float g_M [B*T*D];
__device__ float g_gates[(size_t)B*T*G4];   // 64 MB
__device__ float g_hbuf[2][B*HS];
__device__ unsigned g_bar;

// ---------------- init: reset barrier counter + h0 ----------------
__global__ void k_init() {
    int tid = threadIdx.x;
    if (tid == 0) g_bar = 0u;
    for (int i = tid; i < 2*B*HS; i += blockDim.x)
        ((float*)g_hbuf)[i] = 0.f;
}

// ------- s[b,t,r] = tanh(x@W1 + b1) @ W2 + b2  (8 rows / block) -------
__global__ void k_s(const float* __restrict__ x, const float* __restrict__ w1,
                    const float* __restrict__ b1, const float* __restrict__ w2,
                    const float* __restrict__ b2) {
    __shared__ float xs[8][D];
    __shared__ float h1[8][DA];
    int tid = threadIdx.x;                 // 256
    int row0 = blockIdx.x * 8;             // row = b*T + t
    for (int i = tid; i < 8*D; i += 256)
        xs[i/D][i%D] = x[(size_t)row0*D + i];
    __syncthreads();
    int a = tid & 63, rq = tid >> 6;       // rq: 0..3 -> rows rq, rq+4
    float acc0 = b1[a], acc1 = b1[a];
    #pragma unroll 4
    for (int d = 0; d < D; d++) {
        float w = w1[d*DA + a];            // coalesced across a
        acc0 += xs[rq][d]   * w;
        acc1 += xs[rq+4][d] * w;
    }
    h1[rq][a]   = tanhf(acc0);
    h1[rq+4][a] = tanhf(acc1);
    __syncthreads();
    if (tid < 64) {
        int rr = tid >> 3, r = tid & 7;
        float acc = b2[r];
        #pragma unroll 8
        for (int a2 = 0; a2 < DA; a2++)
            acc += h1[rr][a2] * w2[a2*R + r];
        g_s[(size_t)(row0+rr)*R + r] = acc;
    }
}

// ------- running softmax denominators: e = exp(s), iz = 1/cumsum(e) -------
__global__ void k_cumsum() {
    int tid = threadIdx.x;
    if (tid >= B*R) return;
    int b = tid >> 3, r = tid & 7;
    const float* sp = &g_s [(size_t)b*T*R + r];
    float*       ep = &g_e [(size_t)b*T*R + r];
    float*       zp = &g_iz[(size_t)b*T*R + r];
    float z = 0.f;
    #pragma unroll 4
    for (int t = 0; t < T; t++) {
        float e = expf(sp[t*R]);
        z += e;
        ep[t*R] = e;
        zp[t*R] = 1.0f / z;
    }
}

// ------- M[b,t,d] = (1/R) sum_r iz[t,r] * cumsum_j<=t( e[j,r]*x[j,d] ) -------
__global__ void k_M(const float* __restrict__ x) {
    __shared__ float4 es[T*2];
    __shared__ float4 zs[T*2];
    int b = blockIdx.x >> 1, dh = blockIdx.x & 1;
    int tid = threadIdx.x;                 // 128
    const float4* eg = (const float4*)&g_e [(size_t)b*T*R];
    const float4* zg = (const float4*)&g_iz[(size_t)b*T*R];
    for (int i = tid; i < T*2; i += 128) { es[i] = eg[i]; zs[i] = zg[i]; }
    __syncthreads();
    int d = dh*128 + tid;
    float4 clo = {0,0,0,0}, chi = {0,0,0,0};
    const float* xp = &x[(size_t)b*T*D + d];
    float*       mp = &g_M[(size_t)b*T*D + d];
    for (int t = 0; t < T; t++) {
        float xv = xp[(size_t)t*D];
        float4 ea = es[2*t], eb = es[2*t+1];
        clo.x += ea.x*xv; clo.y += ea.y*xv; clo.z += ea.z*xv; clo.w += ea.w*xv;
        chi.x += eb.x*xv; chi.y += eb.y*xv; chi.z += eb.z*xv; chi.w += eb.w*xv;
        float4 za = zs[2*t], zb = zs[2*t+1];
        float m = clo.x*za.x + clo.y*za.y + clo.z*za.z + clo.w*za.w
                + chi.x*zb.x + chi.y*zb.y + chi.z*zb.z + chi.w*zb.w;
        mp[(size_t)t*D] = m * 0.125f;
    }
}

// ------- gates = M(8192x256) @ W_i(256x2048) + bias -------
#define BM 64
#define BN 64
#define BK 32
__global__ void k_gemm(const float* __restrict__ Wi, const float* __restrict__ bias) {
    __shared__ float As[BK][BM+4];   // +4: transpose-store conflict pad (stride 68, f4-aligned)
    __shared__ float Bs[BK][BN];
    int tid = threadIdx.x;           // 256
    int tx = tid & 15, ty = tid >> 4;
    int rb = blockIdx.y * BM, nb = blockIdx.x * BN;
    float c[4][4] = {};
    for (int kb = 0; kb < D; kb += BK) {
        #pragma unroll
        for (int j = 0; j < 2; j++) {
            int lin = tid + j*256;
            int mm = lin >> 3, kk4 = (lin & 7) * 4;
            float4 v = *(const float4*)&g_M[(size_t)(rb+mm)*D + kb + kk4];
            As[kk4+0][mm] = v.x; As[kk4+1][mm] = v.y;
            As[kk4+2][mm] = v.z; As[kk4+3][mm] = v.w;
        }
        #pragma unroll
        for (int j = 0; j < 2; j++) {
            int lin = tid + j*256;
            int kk = lin >> 4, nn4 = (lin & 15) * 4;
            *(float4*)&Bs[kk][nn4] = *(const float4*)&Wi[(size_t)(kb+kk)*G4 + nb + nn4];
        }
        __syncthreads();
        #pragma unroll
        for (int kk = 0; kk < BK; kk++) {
            float4 av = *(const float4*)&As[kk][ty*4];
            float4 bv = *(const float4*)&Bs[kk][tx*4];
            c[0][0] += av.x*bv.x; c[0][1] += av.x*bv.y; c[0][2] += av.x*bv.z; c[0][3] += av.x*bv.w;
            c[1][0] += av.y*bv.x; c[1][1] += av.y*bv.y; c[1][2] += av.y*bv.z; c[1][3] += av.y*bv.w;
            c[2][0] += av.z*bv.x; c[2][1] += av.z*bv.y; c[2][2] += av.z*bv.z; c[2][3] += av.z*bv.w;
            c[3][0] += av.w*bv.x; c[3][1] += av.w*bv.y; c[3][2] += av.w*bv.z; c[3][3] += av.w*bv.w;
        }
        __syncthreads();
    }
    float4 bv = *(const float4*)&bias[nb + tx*4];
    #pragma unroll
    for (int i = 0; i < 4; i++) {
        int row = rb + ty*4 + i;
        float4 o;
        o.x = c[i][0] + bv.x; o.y = c[i][1] + bv.y;
        o.z = c[i][2] + bv.z; o.w = c[i][3] + bv.w;
        *(float4*)&g_gates[(size_t)row*G4 + nb + tx*4] = o;
    }
}

// ------- persistent LSTM scan: 128 CTAs, CTA k owns h-indices [4k,4k+4) -------
__global__ void __launch_bounds__(SCAN_THREADS, 1)
k_scan(const float* __restrict__ Whh, float* __restrict__ out) {
    extern __shared__ float sm[];
    float* Wsh = sm;                       // [16][HPAD]  c-major, h minor
    float* Hsh = sm + 16*HPAD;             // [16][HPAD]  b-major, h minor
    float* ps  = sm + 2*16*HPAD;           // [2][256] partial sums
    int tid = threadIdx.x;
    int k = blockIdx.x;
    int c = tid & 15, b = (tid >> 4) & 15, half = tid >> 8;

    // stage W_hh slice (once per launch): 16 cols x 512 rows = 32 KB
    for (int idx = tid; idx < 16*HS; idx += SCAN_THREADS) {
        int h = idx >> 4, cc = idx & 15;
        int col = (cc >> 2)*HS + k*4 + (cc & 3);   // gate*512 + j
        Wsh[cc*HPAD + h] = Whh[(size_t)h*G4 + col];
    }
    // stage h0 (zeros)
    {
        const float4* hb = (const float4*)&g_hbuf[0][0];
        for (int i = tid; i < (B*HS)/4; i += SCAN_THREADS) {
            float4 v = hb[i];
            int fl = i*4; int bb = fl >> 9; int hh = fl & 511;
            *(float4*)&Hsh[bb*HPAD + hh] = v;
        }
    }
    __syncthreads();

    int gate = c >> 2, jj = c & 3;
    int col = gate*HS + k*4 + jj;
    float creg = 0.f;                      // cell state: only tid<64 use it
    float* hid_out = out;                           // (B,T,HS)
    float* ht_out  = out + (size_t)B*T*HS;          // (B,HS)
    float* ct_out  = ht_out + B*HS;                 // (B,HS)
    const float* Wp  = &Wsh[c*HPAD + half*256];
    const float* Hp  = &Hsh[b*HPAD + half*256];
    const float* gxp = &g_gates[(size_t)b*T*G4 + col];

    for (int t = 0; t < T; t++) {
        float gx = (half == 0) ? gxp[(size_t)t*G4] : 0.f;  // issued early, hidden by dot
        float4 a4 = {0,0,0,0};
        #pragma unroll 8
        for (int hh = 0; hh < 256; hh += 4) {
            float4 w  = *(const float4*)(Wp + hh);
            float4 hv = *(const float4*)(Hp + hh);
            a4.x += w.x*hv.x; a4.y += w.y*hv.y;
            a4.z += w.z*hv.z; a4.w += w.w*hv.w;
        }
        ps[half*256 + b*16 + c] = (a4.x + a4.y) + (a4.z + a4.w) + gx;
        __syncthreads();

        if (tid < 64) {                    // gate fusion: thread = (b, jj)
            int bb = tid >> 2, j2 = tid & 3;
            int base = bb*16;
            float gi = ps[base + j2]      + ps[256 + base + j2];
            float gf = ps[base + 4 + j2]  + ps[256 + base + 4 + j2];
            float gg = ps[base + 8 + j2]  + ps[256 + base + 8 + j2];
            float go = ps[base + 12 + j2] + ps[256 + base + 12 + j2];
            float iv = 1.f/(1.f + expf(-gi));
            float fv = 1.f/(1.f + expf(-gf));
            float gv = tanhf(gg);
            float ov = 1.f/(1.f + expf(-go));
            creg = fv*creg + iv*gv;
            float hv = ov * tanhf(creg);
            int hj = k*4 + j2;
            hid_out[((size_t)bb*T + t)*HS + hj] = hv;
            g_hbuf[(t+1)&1][bb*HS + hj] = hv;
            if (t == T-1) { ht_out[bb*HS + hj] = hv; ct_out[bb*HS + hj] = creg; }
            __threadfence();               // make h visible device-wide before arrival
        }
        __syncthreads();

        if (tid == 0) {                    // monotonic grid barrier (all CTAs resident)
            atomicAdd(&g_bar, 1u);
            unsigned target = (unsigned)(t+1) * NCTA;
            while (*((volatile unsigned*)&g_bar) < target) { }
            __threadfence();
        }
        __syncthreads();

        // broadcast-load new h (double-buffered: race-free across steps)
        const float4* hb = (const float4*)&g_hbuf[(t+1)&1][0];
        for (int i = tid; i < (B*HS)/4; i += SCAN_THREADS) {
            float4 v = hb[i];
            int fl = i*4; int bb2 = fl >> 9; int hh = fl & 511;
            *(float4*)&Hsh[bb2*HPAD + hh] = v;
        }
        __syncthreads();
    }
}

extern "C" void kernel_launch(void* const* d_in, const int* in_sizes, int n_in,
                              void* d_out, int out_size) {
    const float* x    = (const float*)d_in[0];
    const float* w1   = (const float*)d_in[1];
    const float* b1   = (const float*)d_in[2];
    const float* w2   = (const float*)d_in[3];
    const float* b2   = (const float*)d_in[4];
    const float* Wi   = (const float*)d_in[5];
    const float* Whh  = (const float*)d_in[6];
    const float* bias = (const float*)d_in[7];
    float* out = (float*)d_out;

    (void)in_sizes; (void)n_in; (void)out_size;

    k_init<<<1, 256>>>();
    k_s<<<(B*T)/8, 256>>>(x, w1, b1, w2, b2);
    k_cumsum<<<1, 128>>>();
    k_M<<<32, 128>>>(x);
    dim3 gg(G4/BN, (B*T)/BM);
    k_gemm<<<gg, 256>>>(Wi, bias);

    size_t smem = (size_t)(2*16*HPAD + 2*256) * sizeof(float);   // 68,096 B
    cudaFuncSetAttribute(k_scan, cudaFuncAttributeMaxDynamicSharedMemorySize, (int)smem);
    k_scan<<<NCTA, SCAN_THREADS, smem>>>(Whh, out);
}

// round 3
// speedup vs baseline: 1.4170x; 1.4170x over previous
#include <cuda_runtime.h>

#define B 16
#define T 512
#define D 256
#define HS 512
#define DA 64
#define R 8
#define G4 2048
#define NCTA 128
#define SCAN_THREADS 512

// -------- scratch (static device arrays: allocation-free) --------
__device__ float g_s [B*T*R];
__device__ float g_e [B*T*R];
__device__ float g_iz[B*T*R];
__device__ float g_M [B*T*D];
__device__ float g_gates[(size_t)B*T*G4];        // 64 MB
__device__ float g_hbuf[2][HS*B];                // [h][b] transposed, double-buffered
__device__ unsigned g_arrive[NCTA*32];           // barrier slots, 128B stride

// ---- packed f32x2 helpers (Blackwell FFMA2: 2 MACs / inst) ----
__device__ __forceinline__ void ffma2(unsigned long long& d, unsigned long long a, unsigned long long b){
    asm("fma.rn.f32x2 %0, %1, %2, %0;" : "+l"(d) : "l"(a), "l"(b));
}
__device__ __forceinline__ unsigned long long pack2(float x){
    unsigned long long r;
    asm("mov.b64 %0, {%1, %1};" : "=l"(r) : "r"(__float_as_uint(x)));
    return r;
}
__device__ __forceinline__ float lo2(unsigned long long v){ return __uint_as_float((unsigned)v); }
__device__ __forceinline__ float hi2(unsigned long long v){ return __uint_as_float((unsigned)(v>>32)); }

// ---------------- init: reset barrier slots + h0 ----------------
__global__ void k_init() {
    int tid = threadIdx.x;
    for (int i = tid; i < 2*HS*B; i += blockDim.x)
        ((float*)g_hbuf)[i] = 0.f;
    for (int i = tid; i < NCTA*32; i += blockDim.x)
        g_arrive[i] = 0u;
}

// ------- s[b,t,r] = tanh(x@W1 + b1) @ W2 + b2  (8 rows / block) -------
__global__ void k_s(const float* __restrict__ x, const float* __restrict__ w1,
                    const float* __restrict__ b1, const float* __restrict__ w2,
                    const float* __restrict__ b2) {
    __shared__ float xs[8][D];
    __shared__ float h1[8][DA];
    int tid = threadIdx.x;                 // 256
    int row0 = blockIdx.x * 8;             // row = b*T + t
    for (int i = tid; i < 8*D; i += 256)
        xs[i/D][i%D] = x[(size_t)row0*D + i];
    __syncthreads();
    int a = tid & 63, rq = tid >> 6;
    float acc0 = b1[a], acc1 = b1[a];
    #pragma unroll 4
    for (int d = 0; d < D; d++) {
        float w = w1[d*DA + a];
        acc0 += xs[rq][d]   * w;
        acc1 += xs[rq+4][d] * w;
    }
    h1[rq][a]   = tanhf(acc0);
    h1[rq+4][a] = tanhf(acc1);
    __syncthreads();
    if (tid < 64) {
        int rr = tid >> 3, r = tid & 7;
        float acc = b2[r];
        #pragma unroll 8
        for (int a2 = 0; a2 < DA; a2++)
            acc += h1[rr][a2] * w2[a2*R + r];
        g_s[(size_t)(row0+rr)*R + r] = acc;
    }
}

// ------- running softmax denominators: e = exp(s), iz = 1/cumsum(e) -------
__global__ void k_cumsum() {
    int tid = threadIdx.x;
    if (tid >= B*R) return;
    int b = tid >> 3, r = tid & 7;
    const float* sp = &g_s [(size_t)b*T*R + r];
    float*       ep = &g_e [(size_t)b*T*R + r];
    float*       zp = &g_iz[(size_t)b*T*R + r];
    float z = 0.f;
    #pragma unroll 4
    for (int t = 0; t < T; t++) {
        float e = expf(sp[t*R]);
        z += e;
        ep[t*R] = e;
        zp[t*R] = 1.0f / z;
    }
}

// ------- M[b,t,d] = (1/R) sum_r iz[t,r] * cumsum_j<=t( e[j,r]*x[j,d] ) -------
__global__ void k_M(const float* __restrict__ x) {
    __shared__ float4 es[T*2];
    __shared__ float4 zs[T*2];
    int b = blockIdx.x >> 1, dh = blockIdx.x & 1;
    int tid = threadIdx.x;                 // 128
    const float4* eg = (const float4*)&g_e [(size_t)b*T*R];
    const float4* zg = (const float4*)&g_iz[(size_t)b*T*R];
    for (int i = tid; i < T*2; i += 128) { es[i] = eg[i]; zs[i] = zg[i]; }
    __syncthreads();
    int d = dh*128 + tid;
    float4 clo = {0,0,0,0}, chi = {0,0,0,0};
    const float* xp = &x[(size_t)b*T*D + d];
    float*       mp = &g_M[(size_t)b*T*D + d];
    for (int t = 0; t < T; t += 4) {
        float xv[4];
        #pragma unroll
        for (int u = 0; u < 4; u++) xv[u] = xp[(size_t)(t+u)*D];
        float mo[4];
        #pragma unroll
        for (int u = 0; u < 4; u++) {
            float4 ea = es[2*(t+u)], eb = es[2*(t+u)+1];
            clo.x += ea.x*xv[u]; clo.y += ea.y*xv[u]; clo.z += ea.z*xv[u]; clo.w += ea.w*xv[u];
            chi.x += eb.x*xv[u]; chi.y += eb.y*xv[u]; chi.z += eb.z*xv[u]; chi.w += eb.w*xv[u];
            float4 za = zs[2*(t+u)], zb = zs[2*(t+u)+1];
            mo[u] = (clo.x*za.x + clo.y*za.y + clo.z*za.z + clo.w*za.w
                   + chi.x*zb.x + chi.y*zb.y + chi.z*zb.z + chi.w*zb.w) * 0.125f;
        }
        #pragma unroll
        for (int u = 0; u < 4; u++) mp[(size_t)(t+u)*D] = mo[u];
    }
}

// ------- gates = M(8192x256) @ W_i(256x2048) + bias, FFMA2 inner -------
#define BM 64
#define BN 64
#define BK 32
__global__ void k_gemm(const float* __restrict__ Wi, const float* __restrict__ bias) {
    __shared__ float As[BK][BM+4];
    __shared__ float Bs[BK][BN];
    int tid = threadIdx.x;           // 256
    int tx = tid & 15, ty = tid >> 4;
    int rb = blockIdx.y * BM, nb = blockIdx.x * BN;
    unsigned long long c2[4][2] = {};
    for (int kb = 0; kb < D; kb += BK) {
        #pragma unroll
        for (int j = 0; j < 2; j++) {
            int lin = tid + j*256;
            int mm = lin >> 3, kk4 = (lin & 7) * 4;
            float4 v = *(const float4*)&g_M[(size_t)(rb+mm)*D + kb + kk4];
            As[kk4+0][mm] = v.x; As[kk4+1][mm] = v.y;
            As[kk4+2][mm] = v.z; As[kk4+3][mm] = v.w;
        }
        #pragma unroll
        for (int j = 0; j < 2; j++) {
            int lin = tid + j*256;
            int kk = lin >> 4, nn4 = (lin & 15) * 4;
            *(float4*)&Bs[kk][nn4] = *(const float4*)&Wi[(size_t)(kb+kk)*G4 + nb + nn4];
        }
        __syncthreads();
        #pragma unroll
        for (int kk = 0; kk < BK; kk++) {
            float4 av = *(const float4*)&As[kk][ty*4];
            double2 bd = *(const double2*)&Bs[kk][tx*4];
            unsigned long long bx = (unsigned long long)__double_as_longlong(bd.x);
            unsigned long long by = (unsigned long long)__double_as_longlong(bd.y);
            unsigned long long a0 = pack2(av.x), a1 = pack2(av.y);
            unsigned long long a2 = pack2(av.z), a3 = pack2(av.w);
            ffma2(c2[0][0], a0, bx); ffma2(c2[0][1], a0, by);
            ffma2(c2[1][0], a1, bx); ffma2(c2[1][1], a1, by);
            ffma2(c2[2][0], a2, bx); ffma2(c2[2][1], a2, by);
            ffma2(c2[3][0], a3, bx); ffma2(c2[3][1], a3, by);
        }
        __syncthreads();
    }
    float4 bv = *(const float4*)&bias[nb + tx*4];
    #pragma unroll
    for (int i = 0; i < 4; i++) {
        int row = rb + ty*4 + i;
        float4 o;
        o.x = lo2(c2[i][0]) + bv.x; o.y = hi2(c2[i][0]) + bv.y;
        o.z = lo2(c2[i][1]) + bv.z; o.w = hi2(c2[i][1]) + bv.w;
        *(float4*)&g_gates[(size_t)row*G4 + nb + tx*4] = o;
    }
}

// ---- scoped barrier primitives ----
__device__ __forceinline__ void st_release(unsigned* p, unsigned v){
    asm volatile("st.release.gpu.global.u32 [%0], %1;" :: "l"(p), "r"(v) : "memory");
}
__device__ __forceinline__ unsigned ld_acquire(const unsigned* p){
    unsigned v;
    asm volatile("ld.acquire.gpu.global.u32 %0, [%1];" : "=r"(v) : "l"(p) : "memory");
    return v;
}

// ------- persistent LSTM scan v2 (hardened barrier) -------
// CTA k owns h-indices [4k,4k+4) for all 16 batches.
// Per step: 16(c) x 16(b) x 512(K) register-tiled GEMM, FFMA2 packed math.
// W from SMEM (staged once), H streamed from L2 via __ldcv ([h][b] layout).
// Grid barrier: per-CTA release slots + acquire polls with nanosleep backoff.
__global__ void __launch_bounds__(SCAN_THREADS, 1)
k_scan(const float* __restrict__ Whh, float* __restrict__ out) {
    extern __shared__ float sm[];
    float* Wsh = sm;                  // [512][16]  h-major, 32 KB
    float* red = sm + 8192;           // [32][16][16] partials, 32 KB
    float* sg  = sm + 16384;          // [16][16] reduced pre-activations
    int tid = threadIdx.x;
    int k = blockIdx.x;

    // stage W slice once: Wsh[h][c] = Whh[h][gate*HS + k*4 + jj],  c = gate*4+jj
    for (int idx = tid; idx < HS*16; idx += SCAN_THREADS) {
        int h = idx >> 4, c = idx & 15;
        Wsh[idx] = Whh[(size_t)h*G4 + (c>>2)*HS + k*4 + (c&3)];
    }
    __syncthreads();

    int lane = tid & 31, warp = tid >> 5;
    int cx = lane & 3, by = (lane>>2)&3, ksub = lane>>4;
    int kbase = warp*32 + ksub;            // thread covers k = kbase + 2*i, i<16
    int bb = tid >> 2, j2 = tid & 3;       // fusion mapping (tid<64)
    float creg = 0.f;

    float* hid_out = out;                         // (B,T,HS)
    float* ht_out  = out + (size_t)B*T*HS;        // (B,HS)
    float* ct_out  = ht_out + B*HS;               // (B,HS)
    const float* Wp = Wsh + cx*4;

    for (int t = 0; t < T; t++) {
        // prefetch gates_x for the fusion threads (latency hidden by dot)
        float gx0=0.f, gx1=0.f, gx2=0.f, gx3=0.f;
        if (tid < 64) {
            const float* gp = &g_gates[((size_t)bb*T + t)*G4 + k*4 + j2];
            gx0 = __ldg(gp); gx1 = __ldg(gp + HS);
            gx2 = __ldg(gp + 2*HS); gx3 = __ldg(gp + 3*HS);
        }

        // 4x4 outer-product dot over this thread's 32-k slice
        const float* Hp = &g_hbuf[t&1][0] + by*4;
        unsigned long long acc[4][2] = {};
        #pragma unroll
        for (int i = 0; i < 16; i++) {
            int kk = kbase + i*2;
            float4 w = *(const float4*)(Wp + kk*16);
            double2 hd = __ldcv((const double2*)(Hp + kk*16));   // L2, never stale
            unsigned long long hx = (unsigned long long)__double_as_longlong(hd.x);
            unsigned long long hy = (unsigned long long)__double_as_longlong(hd.y);
            unsigned long long w0 = pack2(w.x), w1 = pack2(w.y);
            unsigned long long w2 = pack2(w.z), w3 = pack2(w.w);
            ffma2(acc[0][0], w0, hx); ffma2(acc[0][1], w0, hy);
            ffma2(acc[1][0], w1, hx); ffma2(acc[1][1], w1, hy);
            ffma2(acc[2][0], w2, hx); ffma2(acc[2][1], w2, hy);
            ffma2(acc[3][0], w3, hx); ffma2(acc[3][1], w3, hy);
        }
        float* rp = red + (warp*2 + ksub)*256 + by*4;
        #pragma unroll
        for (int i = 0; i < 4; i++) {
            float4 v = make_float4(lo2(acc[i][0]), hi2(acc[i][0]),
                                   lo2(acc[i][1]), hi2(acc[i][1]));
            *(float4*)(rp + (cx*4 + i)*16) = v;
        }
        __syncthreads();

        // reduce 32 k-slices: thread tid<256 owns (c = tid>>4, b = tid&15)
        if (tid < 256) {
            float s = 0.f;
            #pragma unroll
            for (int sl = 0; sl < 32; sl++) s += red[sl*256 + tid];
            sg[tid] = s;
        }
        __syncthreads();

        // gate fusion: thread = (bb, j2)
        if (tid < 64) {
            float gi = sg[( 0 + j2)*16 + bb] + gx0;
            float gf = sg[( 4 + j2)*16 + bb] + gx1;
            float gg = sg[( 8 + j2)*16 + bb] + gx2;
            float go = sg[(12 + j2)*16 + bb] + gx3;
            float iv = 1.f/(1.f + __expf(-gi));
            float fv = 1.f/(1.f + __expf(-gf));
            float gv = tanhf(gg);
            float ov = 1.f/(1.f + __expf(-go));
            creg = fv*creg + iv*gv;
            float hv = ov * tanhf(creg);
            int hj = k*4 + j2;
            hid_out[((size_t)bb*T + t)*HS + hj] = hv;
            g_hbuf[(t+1)&1][hj*B + bb] = hv;     // transposed [h][b]
            if (t == T-1) { ht_out[bb*HS + hj] = hv; ct_out[bb*HS + hj] = creg; }
            __threadfence();                     // publish h before arrival
        }
        __syncthreads();

        // grid barrier: per-CTA slots, release/acquire, nanosleep backoff
        if (tid == 0) st_release(&g_arrive[k*32], (unsigned)(t+1));
        if (tid < NCTA) {
            const unsigned* slot = &g_arrive[tid*32];
            while (ld_acquire(slot) < (unsigned)(t+1)) __nanosleep(40);
        }
        __syncthreads();
    }
}

extern "C" void kernel_launch(void* const* d_in, const int* in_sizes, int n_in,
                              void* d_out, int out_size) {
    const float* x    = (const float*)d_in[0];
    const float* w1   = (const float*)d_in[1];
    const float* b1   = (const float*)d_in[2];
    const float* w2   = (const float*)d_in[3];
    const float* b2   = (const float*)d_in[4];
    const float* Wi   = (const float*)d_in[5];
    const float* Whh  = (const float*)d_in[6];
    const float* bias = (const float*)d_in[7];
    float* out = (float*)d_out;

    (void)in_sizes; (void)n_in; (void)out_size;

    k_init<<<1, 256>>>();
    k_s<<<(B*T)/8, 256>>>(x, w1, b1, w2, b2);
    k_cumsum<<<1, 128>>>();
    k_M<<<32, 128>>>(x);
    dim3 gg(G4/BN, (B*T)/BM);
    k_gemm<<<gg, 256>>>(Wi, bias);

    size_t smem = (size_t)(8192 + 8192 + 256) * sizeof(float);   // 66,560 B
    cudaFuncSetAttribute(k_scan, cudaFuncAttributeMaxDynamicSharedMemorySize, (int)smem);
    k_scan<<<NCTA, SCAN_THREADS, smem>>>(Whh, out);
}

// round 4
// speedup vs baseline: 1.6758x; 1.1826x over previous
#include <cuda_runtime.h>

#define B 16
#define T 512
#define D 256
#define HS 512
#define DA 64
#define R 8
#define G4 2048
#define NCTA 128
#define SCAN_THREADS 512
#define TC 64
#define NCH (T/TC)   // 8

// -------- scratch (static device arrays: allocation-free) --------
__device__ float g_s [B*T*R];
__device__ float g_e [B*T*R];
__device__ float g_iz[B*T*R];
__device__ float g_S [B*NCH*R*D];                // per-chunk e*x sums, 1 MB
__device__ float g_M [B*T*D];
__device__ float g_gates[(size_t)B*T*G4];        // 64 MB
__device__ float g_hbuf[2][HS*B];                // [h][b] transposed, double-buffered
__device__ unsigned g_arrive[NCTA*32];           // barrier slots, 128B stride

typedef unsigned long long ull;

// ---- packed f32x2 helpers (Blackwell: 2 MACs / inst) ----
__device__ __forceinline__ void ffma2(ull& d, ull a, ull b){
    asm("fma.rn.f32x2 %0, %1, %2, %0;" : "+l"(d) : "l"(a), "l"(b));
}
__device__ __forceinline__ ull addf2(ull a, ull b){
    ull d; asm("add.rn.f32x2 %0, %1, %2;" : "=l"(d) : "l"(a), "l"(b)); return d;
}
__device__ __forceinline__ ull pack2(float x){
    ull r; asm("mov.b64 %0, {%1, %1};" : "=l"(r) : "r"(__float_as_uint(x))); return r;
}
__device__ __forceinline__ ull dbl2u(double d){ return (ull)__double_as_longlong(d); }
__device__ __forceinline__ float lo2(ull v){ return __uint_as_float((unsigned)v); }
__device__ __forceinline__ float hi2(ull v){ return __uint_as_float((unsigned)(v>>32)); }

__device__ __forceinline__ void st_release(unsigned* p, unsigned v){
    asm volatile("st.release.gpu.global.u32 [%0], %1;" :: "l"(p), "r"(v) : "memory");
}
__device__ __forceinline__ unsigned ld_acquire(const unsigned* p){
    unsigned v;
    asm volatile("ld.acquire.gpu.global.u32 %0, [%1];" : "=r"(v) : "l"(p) : "memory");
    return v;
}

// ---------------- init: reset barrier slots + h0 ----------------
__global__ void k_init() {
    int tid = threadIdx.x;
    for (int i = tid; i < 2*HS*B; i += blockDim.x)
        ((float*)g_hbuf)[i] = 0.f;
    for (int i = tid; i < NCTA*32; i += blockDim.x)
        g_arrive[i] = 0u;
}

// ------- s[b,t,r] = tanh(x@W1 + b1) @ W2 + b2  (8 rows / block) -------
__global__ void k_s(const float* __restrict__ x, const float* __restrict__ w1,
                    const float* __restrict__ b1, const float* __restrict__ w2,
                    const float* __restrict__ b2) {
    __shared__ float xs[8][D];
    __shared__ float h1[8][DA];
    int tid = threadIdx.x;                 // 256
    int row0 = blockIdx.x * 8;             // row = b*T + t
    for (int i = tid; i < 8*D; i += 256)
        xs[i/D][i%D] = x[(size_t)row0*D + i];
    __syncthreads();
    int a = tid & 63, rq = tid >> 6;
    float acc0 = b1[a], acc1 = b1[a];
    #pragma unroll 4
    for (int d = 0; d < D; d++) {
        float w = w1[d*DA + a];
        acc0 += xs[rq][d]   * w;
        acc1 += xs[rq+4][d] * w;
    }
    h1[rq][a]   = tanhf(acc0);
    h1[rq+4][a] = tanhf(acc1);
    __syncthreads();
    if (tid < 64) {
        int rr = tid >> 3, r = tid & 7;
        float acc = b2[r];
        #pragma unroll 8
        for (int a2 = 0; a2 < DA; a2++)
            acc += h1[rr][a2] * w2[a2*R + r];
        g_s[(size_t)(row0+rr)*R + r] = acc;
    }
}

// ------- running softmax denominators: e = exp(s), iz = 1/cumsum(e) -------
__global__ void k_cumsum() {
    int tid = threadIdx.x;
    if (tid >= B*R) return;
    int b = tid >> 3, r = tid & 7;
    const float* sp = &g_s [(size_t)b*T*R + r];
    float*       ep = &g_e [(size_t)b*T*R + r];
    float*       zp = &g_iz[(size_t)b*T*R + r];
    float z = 0.f;
    #pragma unroll 4
    for (int t = 0; t < T; t++) {
        float e = expf(sp[t*R]);
        z += e;
        ep[t*R] = e;
        zp[t*R] = 1.0f / z;
    }
}

// ------- pass 1: per-chunk sums S[b,ch,r,d] = sum_{j in chunk} e[j,r]*x[j,d] -------
__global__ void k_M1(const float* __restrict__ x) {
    __shared__ float es[TC*R];
    int b = blockIdx.x >> 3, ch = blockIdx.x & 7;
    int tid = threadIdx.x;                 // 256
    int t0 = ch*TC;
    for (int i = tid; i < TC*R; i += 256)
        es[i] = g_e[((size_t)b*T + t0)*R + i];
    __syncthreads();
    int d = tid;
    float acc[R] = {};
    const float* xp = &x[((size_t)b*T + t0)*D + d];
    #pragma unroll 4
    for (int j = 0; j < TC; j++) {
        float xv = xp[(size_t)j*D];
        #pragma unroll
        for (int r = 0; r < R; r++) acc[r] += es[j*R + r] * xv;
    }
    float* sp = &g_S[((size_t)(b*NCH + ch)*R)*D + d];
    #pragma unroll
    for (int r = 0; r < R; r++) sp[r*D] = acc[r];
}

// ------- pass 2: within-chunk weighted cumsum, seeded by chunk prefix -------
__global__ void k_M2(const float* __restrict__ x) {
    __shared__ float4 es[TC*2];
    __shared__ float4 zs[TC*2];
    int bi = blockIdx.x;
    int b = bi >> 4, dh = (bi >> 3) & 1, ch = bi & 7;
    int tid = threadIdx.x;                 // 128
    int t0 = ch*TC;
    const float4* eg = (const float4*)&g_e [((size_t)b*T + t0)*R];
    const float4* zg = (const float4*)&g_iz[((size_t)b*T + t0)*R];
    for (int i = tid; i < TC*2; i += 128) { es[i] = eg[i]; zs[i] = zg[i]; }
    __syncthreads();
    int d = dh*128 + tid;
    float4 clo = {0,0,0,0}, chi = {0,0,0,0};
    for (int c = 0; c < ch; c++) {
        const float* sp = &g_S[((size_t)(b*NCH + c)*R)*D + d];
        clo.x += sp[0];   clo.y += sp[D];   clo.z += sp[2*D]; clo.w += sp[3*D];
        chi.x += sp[4*D]; chi.y += sp[5*D]; chi.z += sp[6*D]; chi.w += sp[7*D];
    }
    const float* xp = &x[((size_t)b*T + t0)*D + d];
    float*       mp = &g_M[((size_t)b*T + t0)*D + d];
    for (int j = 0; j < TC; j += 4) {
        float xv[4];
        #pragma unroll
        for (int u = 0; u < 4; u++) xv[u] = xp[(size_t)(j+u)*D];
        float mo[4];
        #pragma unroll
        for (int u = 0; u < 4; u++) {
            float4 ea = es[2*(j+u)], eb = es[2*(j+u)+1];
            clo.x += ea.x*xv[u]; clo.y += ea.y*xv[u]; clo.z += ea.z*xv[u]; clo.w += ea.w*xv[u];
            chi.x += eb.x*xv[u]; chi.y += eb.y*xv[u]; chi.z += eb.z*xv[u]; chi.w += eb.w*xv[u];
            float4 za = zs[2*(j+u)], zb = zs[2*(j+u)+1];
            mo[u] = (clo.x*za.x + clo.y*za.y + clo.z*za.z + clo.w*za.w
                   + chi.x*zb.x + chi.y*zb.y + chi.z*zb.z + chi.w*zb.w) * 0.125f;
        }
        #pragma unroll
        for (int u = 0; u < 4; u++) mp[(size_t)(j+u)*D] = mo[u];
    }
}

// ------- gates = M(8192x256) @ W_i(256x2048) + bias, 128x128x16 / 8x8 tiles -------
#define GBM 128
#define GBN 128
#define GBK 16
__global__ void __launch_bounds__(256)
k_gemm(const float* __restrict__ Wi, const float* __restrict__ bias) {
    __shared__ float As[GBK][GBM+4];   // stride 132 (16B-aligned rows)
    __shared__ float Bs[GBK][GBN+4];
    int tid = threadIdx.x;             // 256
    int tx = tid & 15, ty = tid >> 4;
    int rb = blockIdx.y * GBM, nb = blockIdx.x * GBN;
    ull c2[8][4] = {};
    for (int kb = 0; kb < D; kb += GBK) {
        #pragma unroll
        for (int j = 0; j < 2; j++) {
            int lin = tid + j*256;
            int m = lin >> 2, kq = (lin & 3)*4;
            float4 v = *(const float4*)&g_M[(size_t)(rb+m)*D + kb + kq];
            As[kq+0][m] = v.x; As[kq+1][m] = v.y;
            As[kq+2][m] = v.z; As[kq+3][m] = v.w;
        }
        #pragma unroll
        for (int j = 0; j < 2; j++) {
            int lin = tid + j*256;
            int kk2 = lin >> 5, nq = (lin & 31)*4;
            *(float4*)&Bs[kk2][nq] = *(const float4*)&Wi[(size_t)(kb+kk2)*G4 + nb + nq];
        }
        __syncthreads();
        #pragma unroll
        for (int kk = 0; kk < GBK; kk++) {
            float4 a0 = *(const float4*)&As[kk][ty*8];
            float4 a1 = *(const float4*)&As[kk][ty*8+4];
            double2 b0 = *(const double2*)&Bs[kk][tx*8];
            double2 b1 = *(const double2*)&Bs[kk][tx*8+4];
            ull bx0 = dbl2u(b0.x), bx1 = dbl2u(b0.y);
            ull bx2 = dbl2u(b1.x), bx3 = dbl2u(b1.y);
            float av[8] = {a0.x,a0.y,a0.z,a0.w,a1.x,a1.y,a1.z,a1.w};
            #pragma unroll
            for (int i = 0; i < 8; i++) {
                ull ap = pack2(av[i]);
                ffma2(c2[i][0], ap, bx0); ffma2(c2[i][1], ap, bx1);
                ffma2(c2[i][2], ap, bx2); ffma2(c2[i][3], ap, bx3);
            }
        }
        __syncthreads();
    }
    float4 bv0 = *(const float4*)&bias[nb + tx*8];
    float4 bv1 = *(const float4*)&bias[nb + tx*8 + 4];
    #pragma unroll
    for (int i = 0; i < 8; i++) {
        int row = rb + ty*8 + i;
        float4 o0 = make_float4(lo2(c2[i][0])+bv0.x, hi2(c2[i][0])+bv0.y,
                                lo2(c2[i][1])+bv0.z, hi2(c2[i][1])+bv0.w);
        float4 o1 = make_float4(lo2(c2[i][2])+bv1.x, hi2(c2[i][2])+bv1.y,
                                lo2(c2[i][3])+bv1.z, hi2(c2[i][3])+bv1.w);
        *(float4*)&g_gates[(size_t)row*G4 + nb + tx*8]     = o0;
        *(float4*)&g_gates[(size_t)row*G4 + nb + tx*8 + 4] = o1;
    }
}

// ------- persistent LSTM scan v3 -------
// CTA k owns h-indices [4k,4k+4). W slice lives in REGISTERS (loop-invariant,
// 16 x float4 per thread). H streamed from L2 via __ldcv ([h][b] layout).
// Shfl pre-reduction (ksub pairs) then 16-way smem reduction. No threadfence:
// syncthreads + st.release.gpu is the arrive; ld.acquire.gpu polls.
__global__ void __launch_bounds__(SCAN_THREADS, 1)
k_scan(const float* __restrict__ Whh, float* __restrict__ out) {
    __shared__ float red[16*16*20];   // [warp][c][20-pad b] 20 KB
    __shared__ float sg[256];         // [c][b]
    int tid = threadIdx.x;
    int k = blockIdx.x;
    int lane = tid & 31, warp = tid >> 5;
    int cx = lane & 3, by = (lane>>2)&3, ksub = lane>>4;
    int kbase = warp*32 + ksub;            // thread covers h = kbase + 2*i, i<16
    int bb = tid >> 2, j2 = tid & 3;       // fusion mapping (tid<64)
    float creg = 0.f;

    // preload W slice into registers: wr[i] = Whh[kbase+2i][cx*HS + k*4 .. +3]
    float4 wr[16];
    #pragma unroll
    for (int i = 0; i < 16; i++)
        wr[i] = *(const float4*)&Whh[(size_t)(kbase + 2*i)*G4 + cx*HS + k*4];

    float* hid_out = out;                         // (B,T,HS)
    float* ht_out  = out + (size_t)B*T*HS;        // (B,HS)
    float* ct_out  = ht_out + B*HS;               // (B,HS)

    for (int t = 0; t < T; t++) {
        // prefetch gates_x for the fusion threads (hidden under the dot)
        float gx0=0.f, gx1=0.f, gx2=0.f, gx3=0.f;
        if (tid < 64) {
            const float* gp = &g_gates[((size_t)bb*T + t)*G4 + k*4 + j2];
            gx0 = __ldg(gp); gx1 = __ldg(gp + HS);
            gx2 = __ldg(gp + 2*HS); gx3 = __ldg(gp + 3*HS);
        }

        // 4x4 outer-product dot over this thread's 32-h slice (W in regs)
        const float* Hp = &g_hbuf[t&1][0] + by*4;
        ull acc[4][2] = {};
        #pragma unroll
        for (int i = 0; i < 16; i++) {
            double2 hd = __ldcv((const double2*)(Hp + (kbase + 2*i)*16));
            ull hx = dbl2u(hd.x), hy = dbl2u(hd.y);
            ull w0 = pack2(wr[i].x), w1 = pack2(wr[i].y);
            ull w2 = pack2(wr[i].z), w3 = pack2(wr[i].w);
            ffma2(acc[0][0], w0, hx); ffma2(acc[0][1], w0, hy);
            ffma2(acc[1][0], w1, hx); ffma2(acc[1][1], w1, hy);
            ffma2(acc[2][0], w2, hx); ffma2(acc[2][1], w2, hy);
            ffma2(acc[3][0], w3, hx); ffma2(acc[3][1], w3, hy);
        }
        // reduce ksub pairs via shfl (lanes xor 16 share (cx,by))
        #pragma unroll
        for (int q = 0; q < 4; q++) {
            acc[q][0] = addf2(acc[q][0], __shfl_xor_sync(0xffffffffu, acc[q][0], 16));
            acc[q][1] = addf2(acc[q][1], __shfl_xor_sync(0xffffffffu, acc[q][1], 16));
        }
        if (ksub == 0) {
            float* rp = &red[warp*320 + (cx*4)*20 + by*4];
            #pragma unroll
            for (int q = 0; q < 4; q++) {
                float4 v = make_float4(lo2(acc[q][0]), hi2(acc[q][0]),
                                       lo2(acc[q][1]), hi2(acc[q][1]));
                *(float4*)(rp + q*20) = v;
            }
        }
        __syncthreads();

        // reduce 16 warps: thread tid<256 owns (c = tid>>4, b = tid&15)
        if (tid < 256) {
            int c = tid >> 4, b = tid & 15;
            float s = 0.f;
            #pragma unroll
            for (int w = 0; w < 16; w++) s += red[w*320 + c*20 + b];
            sg[tid] = s;
        }
        __syncthreads();

        // gate fusion: thread = (bb, j2)
        if (tid < 64) {
            float gi = sg[( 0 + j2)*16 + bb] + gx0;
            float gf = sg[( 4 + j2)*16 + bb] + gx1;
            float gg = sg[( 8 + j2)*16 + bb] + gx2;
            float go = sg[(12 + j2)*16 + bb] + gx3;
            float iv = 1.f/(1.f + __expf(-gi));
            float fv = 1.f/(1.f + __expf(-gf));
            float gv = tanhf(gg);
            float ov = 1.f/(1.f + __expf(-go));
            creg = fv*creg + iv*gv;
            float hv = ov * tanhf(creg);
            int hj = k*4 + j2;
            hid_out[((size_t)bb*T + t)*HS + hj] = hv;
            g_hbuf[(t+1)&1][hj*B + bb] = hv;     // transposed [h][b]
            if (t == T-1) { ht_out[bb*HS + hj] = hv; ct_out[bb*HS + hj] = creg; }
        }
        __syncthreads();   // order h writes (cta-wide) before tid0's release

        if (tid == 0) st_release(&g_arrive[k*32], (unsigned)(t+1));
        if (tid < NCTA) {
            const unsigned* slot = &g_arrive[tid*32];
            while (ld_acquire(slot) < (unsigned)(t+1)) __nanosleep(20);
        }
        __syncthreads();
    }
}

extern "C" void kernel_launch(void* const* d_in, const int* in_sizes, int n_in,
                              void* d_out, int out_size) {
    const float* x    = (const float*)d_in[0];
    const float* w1   = (const float*)d_in[1];
    const float* b1   = (const float*)d_in[2];
    const float* w2   = (const float*)d_in[3];
    const float* b2   = (const float*)d_in[4];
    const float* Wi   = (const float*)d_in[5];
    const float* Whh  = (const float*)d_in[6];
    const float* bias = (const float*)d_in[7];
    float* out = (float*)d_out;

    (void)in_sizes; (void)n_in; (void)out_size;

    k_init<<<1, 256>>>();
    k_s<<<(B*T)/8, 256>>>(x, w1, b1, w2, b2);
    k_cumsum<<<1, 128>>>();
    k_M1<<<B*NCH, 256>>>(x);
    k_M2<<<B*2*NCH, 128>>>(x);
    dim3 gg(G4/GBN, (B*T)/GBM);
    k_gemm<<<gg, 256>>>(Wi, bias);
    k_scan<<<NCTA, SCAN_THREADS>>>(Whh, out);
}

// round 5
// speedup vs baseline: 1.6760x; 1.0001x over previous
#include <cuda_runtime.h>

#define B 16
#define T 512
#define D 256
#define HS 512
#define DA 64
#define R 8
#define G4 2048
#define NCTA 128
#define SCAN_THREADS 512
#define TC 64
#define NCH (T/TC)   // 8

// -------- scratch (static device arrays: allocation-free) --------
__device__ float g_s [B*T*R];
__device__ float g_e [B*T*R];
__device__ float g_iz[B*T*R];
__device__ float g_S [B*NCH*R*D];                // per-chunk e*x sums, 1 MB
__device__ float g_M [B*T*D];
__device__ float g_gates[(size_t)B*T*G4];        // 64 MB
__device__ float g_hbuf[2][HS*B];                // [h][b] transposed, double-buffered
__device__ unsigned g_arrive[NCTA*32];           // barrier slots, 128B stride

typedef unsigned long long ull;

// ---- packed f32x2 helpers (Blackwell: 2 MACs / inst) ----
__device__ __forceinline__ void ffma2(ull& d, ull a, ull b){
    asm("fma.rn.f32x2 %0, %1, %2, %0;" : "+l"(d) : "l"(a), "l"(b));
}
__device__ __forceinline__ ull addf2(ull a, ull b){
    ull d; asm("add.rn.f32x2 %0, %1, %2;" : "=l"(d) : "l"(a), "l"(b)); return d;
}
__device__ __forceinline__ ull pack2(float x){
    ull r; asm("mov.b64 %0, {%1, %1};" : "=l"(r) : "r"(__float_as_uint(x))); return r;
}
__device__ __forceinline__ ull dbl2u(double d){ return (ull)__double_as_longlong(d); }
__device__ __forceinline__ float lo2(ull v){ return __uint_as_float((unsigned)v); }
__device__ __forceinline__ float hi2(ull v){ return __uint_as_float((unsigned)(v>>32)); }

__device__ __forceinline__ void st_release(unsigned* p, unsigned v){
    asm volatile("st.release.gpu.global.u32 [%0], %1;" :: "l"(p), "r"(v) : "memory");
}
__device__ __forceinline__ unsigned ld_acquire(const unsigned* p){
    unsigned v;
    asm volatile("ld.acquire.gpu.global.u32 %0, [%1];" : "=r"(v) : "l"(p) : "memory");
    return v;
}

// ---------------- init: reset barrier slots + h0 ----------------
__global__ void k_init() {
    int tid = threadIdx.x;
    for (int i = tid; i < 2*HS*B; i += blockDim.x)
        ((float*)g_hbuf)[i] = 0.f;
    for (int i = tid; i < NCTA*32; i += blockDim.x)
        g_arrive[i] = 0u;
}

// ------- s[b,t,r] = tanh(x@W1 + b1) @ W2 + b2  (8 rows / block) -------
__global__ void k_s(const float* __restrict__ x, const float* __restrict__ w1,
                    const float* __restrict__ b1, const float* __restrict__ w2,
                    const float* __restrict__ b2) {
    __shared__ float xs[8][D];
    __shared__ float h1[8][DA];
    int tid = threadIdx.x;                 // 256
    int row0 = blockIdx.x * 8;             // row = b*T + t
    for (int i = tid; i < 8*D; i += 256)
        xs[i/D][i%D] = x[(size_t)row0*D + i];
    __syncthreads();
    int a = tid & 63, rq = tid >> 6;
    float acc0 = b1[a], acc1 = b1[a];
    #pragma unroll 4
    for (int d = 0; d < D; d++) {
        float w = w1[d*DA + a];
        acc0 += xs[rq][d]   * w;
        acc1 += xs[rq+4][d] * w;
    }
    h1[rq][a]   = tanhf(acc0);
    h1[rq+4][a] = tanhf(acc1);
    __syncthreads();
    if (tid < 64) {
        int rr = tid >> 3, r = tid & 7;
        float acc = b2[r];
        #pragma unroll 8
        for (int a2 = 0; a2 < DA; a2++)
            acc += h1[rr][a2] * w2[a2*R + r];
        g_s[(size_t)(row0+rr)*R + r] = acc;
    }
}

// ------- running softmax denominators: e = exp(s), iz = 1/cumsum(e) -------
__global__ void k_cumsum() {
    int tid = threadIdx.x;
    if (tid >= B*R) return;
    int b = tid >> 3, r = tid & 7;
    const float* sp = &g_s [(size_t)b*T*R + r];
    float*       ep = &g_e [(size_t)b*T*R + r];
    float*       zp = &g_iz[(size_t)b*T*R + r];
    float z = 0.f;
    #pragma unroll 4
    for (int t = 0; t < T; t++) {
        float e = expf(sp[t*R]);
        z += e;
        ep[t*R] = e;
        zp[t*R] = 1.0f / z;
    }
}

// ------- pass 1: per-chunk sums S[b,ch,r,d] = sum_{j in chunk} e[j,r]*x[j,d] -------
__global__ void k_M1(const float* __restrict__ x) {
    __shared__ float es[TC*R];
    int b = blockIdx.x >> 3, ch = blockIdx.x & 7;
    int tid = threadIdx.x;                 // 256
    int t0 = ch*TC;
    for (int i = tid; i < TC*R; i += 256)
        es[i] = g_e[((size_t)b*T + t0)*R + i];
    __syncthreads();
    int d = tid;
    float acc[R] = {};
    const float* xp = &x[((size_t)b*T + t0)*D + d];
    #pragma unroll 4
    for (int j = 0; j < TC; j++) {
        float xv = xp[(size_t)j*D];
        #pragma unroll
        for (int r = 0; r < R; r++) acc[r] += es[j*R + r] * xv;
    }
    float* sp = &g_S[((size_t)(b*NCH + ch)*R)*D + d];
    #pragma unroll
    for (int r = 0; r < R; r++) sp[r*D] = acc[r];
}

// ------- pass 2: within-chunk weighted cumsum, seeded by chunk prefix -------
__global__ void k_M2(const float* __restrict__ x) {
    __shared__ float4 es[TC*2];
    __shared__ float4 zs[TC*2];
    int bi = blockIdx.x;
    int b = bi >> 4, dh = (bi >> 3) & 1, ch = bi & 7;
    int tid = threadIdx.x;                 // 128
    int t0 = ch*TC;
    const float4* eg = (const float4*)&g_e [((size_t)b*T + t0)*R];
    const float4* zg = (const float4*)&g_iz[((size_t)b*T + t0)*R];
    for (int i = tid; i < TC*2; i += 128) { es[i] = eg[i]; zs[i] = zg[i]; }
    __syncthreads();
    int d = dh*128 + tid;
    float4 clo = {0,0,0,0}, chi = {0,0,0,0};
    for (int c = 0; c < ch; c++) {
        const float* sp = &g_S[((size_t)(b*NCH + c)*R)*D + d];
        clo.x += sp[0];   clo.y += sp[D];   clo.z += sp[2*D]; clo.w += sp[3*D];
        chi.x += sp[4*D]; chi.y += sp[5*D]; chi.z += sp[6*D]; chi.w += sp[7*D];
    }
    const float* xp = &x[((size_t)b*T + t0)*D + d];
    float*       mp = &g_M[((size_t)b*T + t0)*D + d];
    for (int j = 0; j < TC; j += 4) {
        float xv[4];
        #pragma unroll
        for (int u = 0; u < 4; u++) xv[u] = xp[(size_t)(j+u)*D];
        float mo[4];
        #pragma unroll
        for (int u = 0; u < 4; u++) {
            float4 ea = es[2*(j+u)], eb = es[2*(j+u)+1];
            clo.x += ea.x*xv[u]; clo.y += ea.y*xv[u]; clo.z += ea.z*xv[u]; clo.w += ea.w*xv[u];
            chi.x += eb.x*xv[u]; chi.y += eb.y*xv[u]; chi.z += eb.z*xv[u]; chi.w += eb.w*xv[u];
            float4 za = zs[2*(j+u)], zb = zs[2*(j+u)+1];
            mo[u] = (clo.x*za.x + clo.y*za.y + clo.z*za.z + clo.w*za.w
                   + chi.x*zb.x + chi.y*zb.y + chi.z*zb.z + chi.w*zb.w) * 0.125f;
        }
        #pragma unroll
        for (int u = 0; u < 4; u++) mp[(size_t)(j+u)*D] = mo[u];
    }
}

// ------- gates = M(8192x256) @ W_i(256x2048) + bias, 128x128x16 / 8x8 tiles -------
#define GBM 128
#define GBN 128
#define GBK 16
__global__ void __launch_bounds__(256)
k_gemm(const float* __restrict__ Wi, const float* __restrict__ bias) {
    __shared__ float As[GBK][GBM+4];
    __shared__ float Bs[GBK][GBN+4];
    int tid = threadIdx.x;             // 256
    int tx = tid & 15, ty = tid >> 4;
    int rb = blockIdx.y * GBM, nb = blockIdx.x * GBN;
    ull c2[8][4] = {};
    for (int kb = 0; kb < D; kb += GBK) {
        #pragma unroll
        for (int j = 0; j < 2; j++) {
            int lin = tid + j*256;
            int m = lin >> 2, kq = (lin & 3)*4;
            float4 v = *(const float4*)&g_M[(size_t)(rb+m)*D + kb + kq];
            As[kq+0][m] = v.x; As[kq+1][m] = v.y;
            As[kq+2][m] = v.z; As[kq+3][m] = v.w;
        }
        #pragma unroll
        for (int j = 0; j < 2; j++) {
            int lin = tid + j*256;
            int kk2 = lin >> 5, nq = (lin & 31)*4;
            *(float4*)&Bs[kk2][nq] = *(const float4*)&Wi[(size_t)(kb+kk2)*G4 + nb + nq];
        }
        __syncthreads();
        #pragma unroll
        for (int kk = 0; kk < GBK; kk++) {
            float4 a0 = *(const float4*)&As[kk][ty*8];
            float4 a1 = *(const float4*)&As[kk][ty*8+4];
            double2 b0 = *(const double2*)&Bs[kk][tx*8];
            double2 b1 = *(const double2*)&Bs[kk][tx*8+4];
            ull bx0 = dbl2u(b0.x), bx1 = dbl2u(b0.y);
            ull bx2 = dbl2u(b1.x), bx3 = dbl2u(b1.y);
            float av[8] = {a0.x,a0.y,a0.z,a0.w,a1.x,a1.y,a1.z,a1.w};
            #pragma unroll
            for (int i = 0; i < 8; i++) {
                ull ap = pack2(av[i]);
                ffma2(c2[i][0], ap, bx0); ffma2(c2[i][1], ap, bx1);
                ffma2(c2[i][2], ap, bx2); ffma2(c2[i][3], ap, bx3);
            }
        }
        __syncthreads();
    }
    float4 bv0 = *(const float4*)&bias[nb + tx*8];
    float4 bv1 = *(const float4*)&bias[nb + tx*8 + 4];
    #pragma unroll
    for (int i = 0; i < 8; i++) {
        int row = rb + ty*8 + i;
        float4 o0 = make_float4(lo2(c2[i][0])+bv0.x, hi2(c2[i][0])+bv0.y,
                                lo2(c2[i][1])+bv0.z, hi2(c2[i][1])+bv0.w);
        float4 o1 = make_float4(lo2(c2[i][2])+bv1.x, hi2(c2[i][2])+bv1.y,
                                lo2(c2[i][3])+bv1.z, hi2(c2[i][3])+bv1.w);
        *(float4*)&g_gates[(size_t)row*G4 + nb + tx*8]     = o0;
        *(float4*)&g_gates[(size_t)row*G4 + nb + tx*8 + 4] = o1;
    }
}

// ------- persistent LSTM scan v4: SMEM-staged H -------
// CTA k owns h-indices [4k,4k+4). W slice in REGISTERS (loop-invariant).
// Per step: H (32 KB, [h][b]) is staged GMEM->SMEM once via __ldcv (fresh,
// no 4x cx redundancy -> L2 traffic 16MB/step -> 4MB/step). Dot reads H
// from SMEM: per-warp addresses are 8 unique 16B segments spanning 128B
// (conflict-free, cx broadcast). FFMA2 packed math.
__global__ void __launch_bounds__(SCAN_THREADS, 1)
k_scan(const float* __restrict__ Whh, float* __restrict__ out) {
    extern __shared__ float sm[];
    float* Hs  = sm;                  // [512][16]  32 KB
    float* red = sm + 8192;           // [16 warps][16 c][20-pad b] 20 KB
    float* sg  = sm + 8192 + 5120;    // [16 c][16 b]
    int tid = threadIdx.x;
    int k = blockIdx.x;
    int lane = tid & 31, warp = tid >> 5;
    int cx = lane & 3, by = (lane>>2)&3, ksub = lane>>4;
    int kbase = warp*32 + ksub;            // thread covers h = kbase + 2*i, i<16
    int bb = tid >> 2, j2 = tid & 3;       // fusion mapping (tid<64)
    float creg = 0.f;

    // preload W slice into registers: wr[i] = Whh[kbase+2i][cx*HS + k*4 .. +3]
    float4 wr[16];
    #pragma unroll
    for (int i = 0; i < 16; i++)
        wr[i] = *(const float4*)&Whh[(size_t)(kbase + 2*i)*G4 + cx*HS + k*4];

    float* hid_out = out;                         // (B,T,HS)
    float* ht_out  = out + (size_t)B*T*HS;        // (B,HS)
    float* ct_out  = ht_out + B*HS;               // (B,HS)

    for (int t = 0; t < T; t++) {
        // prefetch gates_x for fusion threads (hidden under staging+dot)
        float gx0=0.f, gx1=0.f, gx2=0.f, gx3=0.f;
        if (tid < 64) {
            const float* gp = &g_gates[((size_t)bb*T + t)*G4 + k*4 + j2];
            gx0 = __ldg(gp); gx1 = __ldg(gp + HS);
            gx2 = __ldg(gp + 2*HS); gx3 = __ldg(gp + 3*HS);
        }

        // stage H into SMEM (exactly 32 KB, coalesced, L1-bypassing)
        {
            const float4* hb = (const float4*)&g_hbuf[t&1][0];
            float4* hs4 = (float4*)Hs;
            #pragma unroll
            for (int j = 0; j < 4; j++)
                hs4[tid + j*512] = __ldcv(hb + tid + j*512);
        }
        __syncthreads();

        // 4x4 outer-product dot over this thread's 32-h slice (W regs, H smem)
        ull acc[4][2] = {};
        #pragma unroll
        for (int i = 0; i < 16; i++) {
            double2 hd = *(const double2*)&Hs[(kbase + 2*i)*16 + by*4];
            ull hx = dbl2u(hd.x), hy = dbl2u(hd.y);
            ull w0 = pack2(wr[i].x), w1 = pack2(wr[i].y);
            ull w2 = pack2(wr[i].z), w3 = pack2(wr[i].w);
            ffma2(acc[0][0], w0, hx); ffma2(acc[0][1], w0, hy);
            ffma2(acc[1][0], w1, hx); ffma2(acc[1][1], w1, hy);
            ffma2(acc[2][0], w2, hx); ffma2(acc[2][1], w2, hy);
            ffma2(acc[3][0], w3, hx); ffma2(acc[3][1], w3, hy);
        }
        // reduce ksub pairs via shfl (lanes xor 16 share (cx,by))
        #pragma unroll
        for (int q = 0; q < 4; q++) {
            acc[q][0] = addf2(acc[q][0], __shfl_xor_sync(0xffffffffu, acc[q][0], 16));
            acc[q][1] = addf2(acc[q][1], __shfl_xor_sync(0xffffffffu, acc[q][1], 16));
        }
        if (ksub == 0) {
            float* rp = &red[warp*320 + (cx*4)*20 + by*4];
            #pragma unroll
            for (int q = 0; q < 4; q++) {
                float4 v = make_float4(lo2(acc[q][0]), hi2(acc[q][0]),
                                       lo2(acc[q][1]), hi2(acc[q][1]));
                *(float4*)(rp + q*20) = v;
            }
        }
        __syncthreads();

        // reduce 16 warps: thread tid<256 owns (c = tid>>4, b = tid&15)
        if (tid < 256) {
            int c = tid >> 4, b = tid & 15;
            float s = 0.f;
            #pragma unroll
            for (int w = 0; w < 16; w++) s += red[w*320 + c*20 + b];
            sg[tid] = s;
        }
        __syncthreads();

        // gate fusion: thread = (bb, j2)
        if (tid < 64) {
            float gi = sg[( 0 + j2)*16 + bb] + gx0;
            float gf = sg[( 4 + j2)*16 + bb] + gx1;
            float gg = sg[( 8 + j2)*16 + bb] + gx2;
            float go = sg[(12 + j2)*16 + bb] + gx3;
            float iv = 1.f/(1.f + __expf(-gi));
            float fv = 1.f/(1.f + __expf(-gf));
            float gv = tanhf(gg);
            float ov = 1.f/(1.f + __expf(-go));
            creg = fv*creg + iv*gv;
            float hv = ov * tanhf(creg);
            int hj = k*4 + j2;
            hid_out[((size_t)bb*T + t)*HS + hj] = hv;
            g_hbuf[(t+1)&1][hj*B + bb] = hv;     // transposed [h][b]
            if (t == T-1) { ht_out[bb*HS + hj] = hv; ct_out[bb*HS + hj] = creg; }
        }
        __syncthreads();   // order h writes (cta-wide) before tid0's release

        if (tid == 0) st_release(&g_arrive[k*32], (unsigned)(t+1));
        if (tid < NCTA) {
            const unsigned* slot = &g_arrive[tid*32];
            while (ld_acquire(slot) < (unsigned)(t+1)) __nanosleep(20);
        }
        __syncthreads();
    }
}

extern "C" void kernel_launch(void* const* d_in, const int* in_sizes, int n_in,
                              void* d_out, int out_size) {
    const float* x    = (const float*)d_in[0];
    const float* w1   = (const float*)d_in[1];
    const float* b1   = (const float*)d_in[2];
    const float* w2   = (const float*)d_in[3];
    const float* b2   = (const float*)d_in[4];
    const float* Wi   = (const float*)d_in[5];
    const float* Whh  = (const float*)d_in[6];
    const float* bias = (const float*)d_in[7];
    float* out = (float*)d_out;

    (void)in_sizes; (void)n_in; (void)out_size;

    k_init<<<1, 256>>>();
    k_s<<<(B*T)/8, 256>>>(x, w1, b1, w2, b2);
    k_cumsum<<<1, 128>>>();
    k_M1<<<B*NCH, 256>>>(x);
    k_M2<<<B*2*NCH, 128>>>(x);
    dim3 gg(G4/GBN, (B*T)/GBM);
    k_gemm<<<gg, 256>>>(Wi, bias);

    size_t smem = (size_t)(8192 + 5120 + 256) * sizeof(float);   // 54,272 B
    cudaFuncSetAttribute(k_scan, cudaFuncAttributeMaxDynamicSharedMemorySize, (int)smem);
    k_scan<<<NCTA, SCAN_THREADS, smem>>>(Whh, out);
}